// round 9
// baseline (speedup 1.0000x reference)
#include <cuda_runtime.h>
#include <cuda_fp16.h>

#define N_NODES 50000
#define N_EDGES 1600000
#define D 128

#define SCAN_B 1024
#define SCAN_NBLK ((N_NODES + SCAN_B - 1) / SCAN_B)   // 49

// Scratch (allocation-free rule: __device__ globals)
__device__ __half g_feath[N_NODES * D];   // fp16 copy of input features
__device__ __half g_buf0h[N_NODES * D];   // hop-1 output, fp16
__device__ float  g_buf1[N_NODES * D];    // hop-2 output, fp32 (GEMM input)
__device__ int    g_cnt[N_NODES];
__device__ unsigned short g_rank[N_EDGES];
__device__ int    g_rowptr[N_NODES + 1];
__device__ unsigned short g_csr_src[N_EDGES];
__device__ float  g_norm[N_NODES];
__device__ int    g_blocksum[SCAN_NBLK];

// ---------------------------------------------------------------------------
// Convert feat fp32 -> fp16 (coalesced; 4 floats per thread).
// ---------------------------------------------------------------------------
__global__ void k_cvt(const float* __restrict__ feat) {
    int i = blockIdx.x * blockDim.x + threadIdx.x;
    const int total4 = N_NODES * D / 4;
    if (i >= total4) return;
    float4 v = ((const float4*)feat)[i];
    __half2 h0 = __floats2half2_rn(v.x, v.y);
    __half2 h1 = __floats2half2_rn(v.z, v.w);
    uint2 u;
    u.x = *(unsigned int*)&h0;
    u.y = *(unsigned int*)&h1;
    ((uint2*)g_feath)[i] = u;
}

// ---------------------------------------------------------------------------
// Degree histogram; atomic return value = this edge's rank within its dst.
// ---------------------------------------------------------------------------
__global__ void k_deg_rank(const int* __restrict__ dst) {
    int e = blockIdx.x * blockDim.x + threadIdx.x;
    if (e < N_EDGES) {
        g_rank[e] = (unsigned short)atomicAdd(&g_cnt[dst[e]], 1);
    }
}

// ---------------------------------------------------------------------------
// Scan pass 1: per-block exclusive scan of g_cnt into g_rowptr, block totals.
// ---------------------------------------------------------------------------
__global__ void __launch_bounds__(SCAN_B) k_scan1() {
    __shared__ int sh[SCAN_B];
    int i = blockIdx.x * SCAN_B + threadIdx.x;
    int v = (i < N_NODES) ? g_cnt[i] : 0;
    sh[threadIdx.x] = v;
    __syncthreads();
#pragma unroll
    for (int off = 1; off < SCAN_B; off <<= 1) {
        int t = (threadIdx.x >= off) ? sh[threadIdx.x - off] : 0;
        __syncthreads();
        sh[threadIdx.x] += t;
        __syncthreads();
    }
    if (i < N_NODES) g_rowptr[i] = sh[threadIdx.x] - v;  // exclusive, local
    if (threadIdx.x == SCAN_B - 1) g_blocksum[blockIdx.x] = sh[SCAN_B - 1];
}

// ---------------------------------------------------------------------------
// Scan pass 2: block offsets via shared atomics, + norm, close rowptr.
// ---------------------------------------------------------------------------
__global__ void __launch_bounds__(SCAN_B) k_scan2() {
    __shared__ int off;
    int t = threadIdx.x;
    if (t == 0) off = 0;
    __syncthreads();
    if (t < SCAN_NBLK && t < blockIdx.x) atomicAdd(&off, g_blocksum[t]);
    __syncthreads();
    int o = off;
    int i = blockIdx.x * SCAN_B + t;
    if (i < N_NODES) {
        g_rowptr[i] += o;
        g_norm[i] = rsqrtf(fmaxf((float)g_cnt[i], 1.0f));
    }
    if (i == 0) g_rowptr[N_NODES] = N_EDGES;
}

// ---------------------------------------------------------------------------
// CSR fill: atomic-free scatter using precomputed ranks (1 edge/thread,
// known-good shape).
// ---------------------------------------------------------------------------
__global__ void k_fill(const int* __restrict__ src,
                       const int* __restrict__ dst) {
    int e = blockIdx.x * blockDim.x + threadIdx.x;
    if (e < N_EDGES) {
        int d = dst[e];
        g_csr_src[g_rowptr[d] + g_rank[e]] = (unsigned short)src[e];
    }
}

// ---------------------------------------------------------------------------
// Hop: gather fp16 rows (256 B/row), accumulate fp32, warp per dst node.
//   out = norm[d] * sum norm[s] * in[s]
// HOP=1: in = g_feath, out = g_buf0h (fp16)
// HOP=2: in = g_buf0h, out = g_buf1  (fp32)
// ---------------------------------------------------------------------------
template <int HOP>
__global__ void __launch_bounds__(256) k_hop() {
    int w    = (blockIdx.x * blockDim.x + threadIdx.x) >> 5;
    int lane = threadIdx.x & 31;
    if (w >= N_NODES) return;

    const uint2* in2 = (const uint2*)((HOP == 1) ? g_feath : g_buf0h);

    int beg = g_rowptr[w];
    int end = g_rowptr[w + 1];
    float4 acc = make_float4(0.f, 0.f, 0.f, 0.f);
    int e = beg;
    for (; e + 4 <= end; e += 4) {
        int s0 = __ldg(&g_csr_src[e + 0]), s1 = __ldg(&g_csr_src[e + 1]);
        int s2 = __ldg(&g_csr_src[e + 2]), s3 = __ldg(&g_csr_src[e + 3]);
        float n0 = __ldg(&g_norm[s0]), n1 = __ldg(&g_norm[s1]);
        float n2 = __ldg(&g_norm[s2]), n3 = __ldg(&g_norm[s3]);
        uint2 u0 = __ldg(in2 + s0 * 32 + lane);
        uint2 u1 = __ldg(in2 + s1 * 32 + lane);
        uint2 u2 = __ldg(in2 + s2 * 32 + lane);
        uint2 u3 = __ldg(in2 + s3 * 32 + lane);
        float2 a0 = __half22float2(*(__half2*)&u0.x), b0 = __half22float2(*(__half2*)&u0.y);
        float2 a1 = __half22float2(*(__half2*)&u1.x), b1 = __half22float2(*(__half2*)&u1.y);
        float2 a2 = __half22float2(*(__half2*)&u2.x), b2 = __half22float2(*(__half2*)&u2.y);
        float2 a3 = __half22float2(*(__half2*)&u3.x), b3 = __half22float2(*(__half2*)&u3.y);
        acc.x += n0 * a0.x + n1 * a1.x + n2 * a2.x + n3 * a3.x;
        acc.y += n0 * a0.y + n1 * a1.y + n2 * a2.y + n3 * a3.y;
        acc.z += n0 * b0.x + n1 * b1.x + n2 * b2.x + n3 * b3.x;
        acc.w += n0 * b0.y + n1 * b1.y + n2 * b2.y + n3 * b3.y;
    }
    for (; e < end; e++) {
        int s = __ldg(&g_csr_src[e]);
        float ns = __ldg(&g_norm[s]);
        uint2 u = __ldg(in2 + s * 32 + lane);
        float2 a = __half22float2(*(__half2*)&u.x);
        float2 b = __half22float2(*(__half2*)&u.y);
        acc.x += ns * a.x; acc.y += ns * a.y;
        acc.z += ns * b.x; acc.w += ns * b.y;
    }
    float nd = g_norm[w];
    acc.x *= nd; acc.y *= nd; acc.z *= nd; acc.w *= nd;

    if (HOP == 1) {
        __half2 h0 = __floats2half2_rn(acc.x, acc.y);
        __half2 h1 = __floats2half2_rn(acc.z, acc.w);
        uint2 u;
        u.x = *(unsigned int*)&h0;
        u.y = *(unsigned int*)&h1;
        ((uint2*)g_buf0h)[w * 32 + lane] = u;
    } else {
        ((float4*)g_buf1)[w * 32 + lane] = acc;
    }
}

// ---------------------------------------------------------------------------
// GEMM: out[n][o] = sum_k buf1[n][k] * W[o][k] + b[o]  (known-good 64x128 tile)
// ---------------------------------------------------------------------------
#define BM 64
#define BK 32
__global__ void __launch_bounds__(256) k_gemm(const float* __restrict__ W,
                                              const float* __restrict__ bias,
                                              float* __restrict__ out) {
    __shared__ float As[BK][BM + 1];
    __shared__ float Bs[BK][D + 1];

    int t  = threadIdx.x;
    int tx = t & 15;
    int ty = t >> 4;
    int row0 = blockIdx.x * BM;

    float acc[4][8];
#pragma unroll
    for (int i = 0; i < 4; i++)
#pragma unroll
        for (int j = 0; j < 8; j++) acc[i][j] = 0.f;

    for (int k0 = 0; k0 < D; k0 += BK) {
#pragma unroll
        for (int i = 0; i < 8; i++) {
            int idx = t + i * 256;
            int r  = idx >> 5;
            int kk = idx & 31;
            int rg = row0 + r;
            float v = 0.f;
            if (rg < N_NODES) v = g_buf1[(size_t)rg * D + k0 + kk];
            As[kk][r] = v;
        }
#pragma unroll
        for (int i = 0; i < 16; i++) {
            int idx = t + i * 256;
            int o  = idx >> 5;
            int kk = idx & 31;
            Bs[kk][o] = W[o * D + k0 + kk];
        }
        __syncthreads();

#pragma unroll
        for (int kk = 0; kk < BK; kk++) {
            float a[4], bv[8];
#pragma unroll
            for (int i = 0; i < 4; i++) a[i] = As[kk][ty * 4 + i];
#pragma unroll
            for (int j = 0; j < 8; j++) bv[j] = Bs[kk][tx + 16 * j];
#pragma unroll
            for (int i = 0; i < 4; i++)
#pragma unroll
                for (int j = 0; j < 8; j++) acc[i][j] += a[i] * bv[j];
        }
        __syncthreads();
    }

#pragma unroll
    for (int i = 0; i < 4; i++) {
        int rg = row0 + ty * 4 + i;
        if (rg >= N_NODES) continue;
#pragma unroll
        for (int j = 0; j < 8; j++) {
            int c = tx + 16 * j;
            out[(size_t)rg * D + c] = acc[i][j] + bias[c];
        }
    }
}

// ---------------------------------------------------------------------------
// kernel_launch
// ---------------------------------------------------------------------------
extern "C" void kernel_launch(void* const* d_in, const int* in_sizes, int n_in,
                              void* d_out, int out_size) {
    const float* feat = (const float*)d_in[0];
    const int*   src  = (const int*)d_in[1];
    const int*   dst  = (const int*)d_in[2];
    const float* W    = (const float*)d_in[3];
    const float* bias = (const float*)d_in[4];
    float*       out  = (float*)d_out;

    const int gEdge = (N_EDGES + 255) / 256;
    const int gCvt  = (N_NODES * D / 4 + 255) / 256;
    const int gHop  = (N_NODES * 32 + 255) / 256;   // warp per node
    const int gGemm = (N_NODES + BM - 1) / BM;

    void* p = nullptr;
    cudaGetSymbolAddress(&p, g_cnt);
    cudaMemsetAsync(p, 0, N_NODES * sizeof(int), 0);

    k_cvt     <<<gCvt, 256>>>(feat);     // feat fp32 -> g_feath fp16
    k_deg_rank<<<gEdge, 256>>>(dst);
    k_scan1   <<<SCAN_NBLK, SCAN_B>>>();
    k_scan2   <<<SCAN_NBLK, SCAN_B>>>();
    k_fill    <<<gEdge, 256>>>(src, dst);
    k_hop<1>  <<<gHop, 256>>>();         // g_feath -> g_buf0h (fp16)
    k_hop<2>  <<<gHop, 256>>>();         // g_buf0h -> g_buf1  (fp32)
    k_gemm    <<<gGemm, 256>>>(W, bias, out);
}

// round 10
// speedup vs baseline: 1.5472x; 1.5472x over previous
#include <cuda_runtime.h>
#include <cuda_fp16.h>

#define N_NODES 50000
#define N_EDGES 1600000
#define D 128

#define SCAN_B 1024
#define SCAN_NBLK ((N_NODES + SCAN_B - 1) / SCAN_B)   // 49

// Scratch (allocation-free rule: __device__ globals)
__device__ __half g_buf0h[N_NODES * D];   // hop-1 output, fp16
__device__ float  g_buf1[N_NODES * D];    // hop-2 output, fp32 (GEMM input)
__device__ int    g_cnt[N_NODES];
__device__ int    g_rank[N_EDGES];
__device__ int    g_rowptr[N_NODES + 1];
__device__ int    g_csr_src[N_EDGES];
__device__ float  g_norm[N_NODES];
__device__ int    g_blocksum[SCAN_NBLK];

// ---------------------------------------------------------------------------
// Degree histogram; atomic return value = this edge's rank within its dst.
// ---------------------------------------------------------------------------
__global__ void k_deg_rank(const int* __restrict__ dst) {
    int e = blockIdx.x * blockDim.x + threadIdx.x;
    if (e < N_EDGES) {
        g_rank[e] = atomicAdd(&g_cnt[dst[e]], 1);
    }
}

// ---------------------------------------------------------------------------
// Scan pass 1: per-block exclusive scan of g_cnt into g_rowptr, block totals.
// ---------------------------------------------------------------------------
__global__ void __launch_bounds__(SCAN_B) k_scan1() {
    __shared__ int sh[SCAN_B];
    int i = blockIdx.x * SCAN_B + threadIdx.x;
    int v = (i < N_NODES) ? g_cnt[i] : 0;
    sh[threadIdx.x] = v;
    __syncthreads();
#pragma unroll
    for (int off = 1; off < SCAN_B; off <<= 1) {
        int t = (threadIdx.x >= off) ? sh[threadIdx.x - off] : 0;
        __syncthreads();
        sh[threadIdx.x] += t;
        __syncthreads();
    }
    if (i < N_NODES) g_rowptr[i] = sh[threadIdx.x] - v;  // exclusive, local
    if (threadIdx.x == SCAN_B - 1) g_blocksum[blockIdx.x] = sh[SCAN_B - 1];
}

// ---------------------------------------------------------------------------
// Scan pass 2: block offsets via shared atomics, + norm, close rowptr.
// ---------------------------------------------------------------------------
__global__ void __launch_bounds__(SCAN_B) k_scan2() {
    __shared__ int off;
    int t = threadIdx.x;
    if (t == 0) off = 0;
    __syncthreads();
    if (t < SCAN_NBLK && t < blockIdx.x) atomicAdd(&off, g_blocksum[t]);
    __syncthreads();
    int o = off;
    int i = blockIdx.x * SCAN_B + t;
    if (i < N_NODES) {
        g_rowptr[i] += o;
        g_norm[i] = rsqrtf(fmaxf((float)g_cnt[i], 1.0f));
    }
    if (i == 0) g_rowptr[N_NODES] = N_EDGES;
}

// ---------------------------------------------------------------------------
// CSR fill: atomic-free scatter, 1 edge/thread (R7 proven shape, 16.9us).
// ---------------------------------------------------------------------------
__global__ void k_fill(const int* __restrict__ src,
                       const int* __restrict__ dst) {
    int e = blockIdx.x * blockDim.x + threadIdx.x;
    if (e < N_EDGES) {
        int d = dst[e];
        g_csr_src[g_rowptr[d] + g_rank[e]] = src[e];
    }
}

// ---------------------------------------------------------------------------
// Hop 1: gather fp32 feat rows, write fp16.
//   out[d] = norm[d] * sum_{s in N(d)} norm[s] * feat[s]
// Warp per dst node; lane carries 4 columns.
// ---------------------------------------------------------------------------
__global__ void __launch_bounds__(256) k_hop1(const float* __restrict__ feat) {
    int w    = (blockIdx.x * blockDim.x + threadIdx.x) >> 5;
    int lane = threadIdx.x & 31;
    if (w >= N_NODES) return;

    int beg = g_rowptr[w];
    int end = g_rowptr[w + 1];
    float4 acc = make_float4(0.f, 0.f, 0.f, 0.f);
    const float4* in4 = (const float4*)feat;
    int e = beg;
    for (; e + 4 <= end; e += 4) {
        int s0 = __ldg(&g_csr_src[e + 0]), s1 = __ldg(&g_csr_src[e + 1]);
        int s2 = __ldg(&g_csr_src[e + 2]), s3 = __ldg(&g_csr_src[e + 3]);
        float n0 = __ldg(&g_norm[s0]), n1 = __ldg(&g_norm[s1]);
        float n2 = __ldg(&g_norm[s2]), n3 = __ldg(&g_norm[s3]);
        float4 v0 = __ldg(in4 + s0 * 32 + lane);
        float4 v1 = __ldg(in4 + s1 * 32 + lane);
        float4 v2 = __ldg(in4 + s2 * 32 + lane);
        float4 v3 = __ldg(in4 + s3 * 32 + lane);
        acc.x += n0 * v0.x + n1 * v1.x + n2 * v2.x + n3 * v3.x;
        acc.y += n0 * v0.y + n1 * v1.y + n2 * v2.y + n3 * v3.y;
        acc.z += n0 * v0.z + n1 * v1.z + n2 * v2.z + n3 * v3.z;
        acc.w += n0 * v0.w + n1 * v1.w + n2 * v2.w + n3 * v3.w;
    }
    for (; e < end; e++) {
        int s = __ldg(&g_csr_src[e]);
        float ns = __ldg(&g_norm[s]);
        float4 v = __ldg(in4 + s * 32 + lane);
        acc.x += ns * v.x; acc.y += ns * v.y;
        acc.z += ns * v.z; acc.w += ns * v.w;
    }
    float nd = g_norm[w];
    acc.x *= nd; acc.y *= nd; acc.z *= nd; acc.w *= nd;

    __half2 h0 = __floats2half2_rn(acc.x, acc.y);
    __half2 h1 = __floats2half2_rn(acc.z, acc.w);
    uint2 u;
    u.x = *(unsigned int*)&h0;
    u.y = *(unsigned int*)&h1;
    ((uint2*)g_buf0h)[w * 32 + lane] = u;   // 8 bytes per lane
}

// ---------------------------------------------------------------------------
// Hop 2: gather fp16 rows (256 B/row), accumulate fp32, write fp32.
// ---------------------------------------------------------------------------
__global__ void __launch_bounds__(256) k_hop2() {
    int w    = (blockIdx.x * blockDim.x + threadIdx.x) >> 5;
    int lane = threadIdx.x & 31;
    if (w >= N_NODES) return;

    int beg = g_rowptr[w];
    int end = g_rowptr[w + 1];
    float4 acc = make_float4(0.f, 0.f, 0.f, 0.f);
    const uint2* in2 = (const uint2*)g_buf0h;   // 32 uint2 per row
    int e = beg;
    for (; e + 4 <= end; e += 4) {
        int s0 = __ldg(&g_csr_src[e + 0]), s1 = __ldg(&g_csr_src[e + 1]);
        int s2 = __ldg(&g_csr_src[e + 2]), s3 = __ldg(&g_csr_src[e + 3]);
        float n0 = __ldg(&g_norm[s0]), n1 = __ldg(&g_norm[s1]);
        float n2 = __ldg(&g_norm[s2]), n3 = __ldg(&g_norm[s3]);
        uint2 u0 = __ldg(in2 + s0 * 32 + lane);
        uint2 u1 = __ldg(in2 + s1 * 32 + lane);
        uint2 u2 = __ldg(in2 + s2 * 32 + lane);
        uint2 u3 = __ldg(in2 + s3 * 32 + lane);
        float2 a0 = __half22float2(*(__half2*)&u0.x), b0 = __half22float2(*(__half2*)&u0.y);
        float2 a1 = __half22float2(*(__half2*)&u1.x), b1 = __half22float2(*(__half2*)&u1.y);
        float2 a2 = __half22float2(*(__half2*)&u2.x), b2 = __half22float2(*(__half2*)&u2.y);
        float2 a3 = __half22float2(*(__half2*)&u3.x), b3 = __half22float2(*(__half2*)&u3.y);
        acc.x += n0 * a0.x + n1 * a1.x + n2 * a2.x + n3 * a3.x;
        acc.y += n0 * a0.y + n1 * a1.y + n2 * a2.y + n3 * a3.y;
        acc.z += n0 * b0.x + n1 * b1.x + n2 * b2.x + n3 * b3.x;
        acc.w += n0 * b0.y + n1 * b1.y + n2 * b2.y + n3 * b3.y;
    }
    for (; e < end; e++) {
        int s = __ldg(&g_csr_src[e]);
        float ns = __ldg(&g_norm[s]);
        uint2 u = __ldg(in2 + s * 32 + lane);
        float2 a = __half22float2(*(__half2*)&u.x);
        float2 b = __half22float2(*(__half2*)&u.y);
        acc.x += ns * a.x; acc.y += ns * a.y;
        acc.z += ns * b.x; acc.w += ns * b.y;
    }
    float nd = g_norm[w];
    acc.x *= nd; acc.y *= nd; acc.z *= nd; acc.w *= nd;
    ((float4*)g_buf1)[w * 32 + lane] = acc;
}

// ---------------------------------------------------------------------------
// GEMM: out[n][o] = sum_k buf1[n][k] * W[o][k] + b[o]  (known-good 64x128 tile)
// ---------------------------------------------------------------------------
#define BM 64
#define BK 32
__global__ void __launch_bounds__(256) k_gemm(const float* __restrict__ W,
                                              const float* __restrict__ bias,
                                              float* __restrict__ out) {
    __shared__ float As[BK][BM + 1];
    __shared__ float Bs[BK][D + 1];

    int t  = threadIdx.x;
    int tx = t & 15;
    int ty = t >> 4;
    int row0 = blockIdx.x * BM;

    float acc[4][8];
#pragma unroll
    for (int i = 0; i < 4; i++)
#pragma unroll
        for (int j = 0; j < 8; j++) acc[i][j] = 0.f;

    for (int k0 = 0; k0 < D; k0 += BK) {
#pragma unroll
        for (int i = 0; i < 8; i++) {
            int idx = t + i * 256;
            int r  = idx >> 5;
            int kk = idx & 31;
            int rg = row0 + r;
            float v = 0.f;
            if (rg < N_NODES) v = g_buf1[(size_t)rg * D + k0 + kk];
            As[kk][r] = v;
        }
#pragma unroll
        for (int i = 0; i < 16; i++) {
            int idx = t + i * 256;
            int o  = idx >> 5;
            int kk = idx & 31;
            Bs[kk][o] = W[o * D + k0 + kk];
        }
        __syncthreads();

#pragma unroll
        for (int kk = 0; kk < BK; kk++) {
            float a[4], bv[8];
#pragma unroll
            for (int i = 0; i < 4; i++) a[i] = As[kk][ty * 4 + i];
#pragma unroll
            for (int j = 0; j < 8; j++) bv[j] = Bs[kk][tx + 16 * j];
#pragma unroll
            for (int i = 0; i < 4; i++)
#pragma unroll
                for (int j = 0; j < 8; j++) acc[i][j] += a[i] * bv[j];
        }
        __syncthreads();
    }

#pragma unroll
    for (int i = 0; i < 4; i++) {
        int rg = row0 + ty * 4 + i;
        if (rg >= N_NODES) continue;
#pragma unroll
        for (int j = 0; j < 8; j++) {
            int c = tx + 16 * j;
            out[(size_t)rg * D + c] = acc[i][j] + bias[c];
        }
    }
}

// ---------------------------------------------------------------------------
// kernel_launch
// ---------------------------------------------------------------------------
extern "C" void kernel_launch(void* const* d_in, const int* in_sizes, int n_in,
                              void* d_out, int out_size) {
    const float* feat = (const float*)d_in[0];
    const int*   src  = (const int*)d_in[1];
    const int*   dst  = (const int*)d_in[2];
    const float* W    = (const float*)d_in[3];
    const float* bias = (const float*)d_in[4];
    float*       out  = (float*)d_out;

    const int gEdge = (N_EDGES + 255) / 256;
    const int gHop  = (N_NODES * 32 + 255) / 256;   // warp per node
    const int gGemm = (N_NODES + BM - 1) / BM;

    void* p = nullptr;
    cudaGetSymbolAddress(&p, g_cnt);
    cudaMemsetAsync(p, 0, N_NODES * sizeof(int), 0);

    k_deg_rank<<<gEdge, 256>>>(dst);
    k_scan1   <<<SCAN_NBLK, SCAN_B>>>();
    k_scan2   <<<SCAN_NBLK, SCAN_B>>>();
    k_fill    <<<gEdge, 256>>>(src, dst);
    k_hop1    <<<gHop, 256>>>(feat);    // feat (fp32) -> g_buf0h (fp16)
    k_hop2    <<<gHop, 256>>>();        // g_buf0h     -> g_buf1 (fp32)
    k_gemm    <<<gGemm, 256>>>(W, bias, out);
}

// round 11
// speedup vs baseline: 1.6629x; 1.0748x over previous
#include <cuda_runtime.h>
#include <cuda_fp16.h>
#include <mma.h>

using namespace nvcuda;

#define N_NODES 50000
#define N_EDGES 1600000
#define D 128

#define SCAN_B 1024
#define SCAN_NBLK ((N_NODES + SCAN_B - 1) / SCAN_B)   // 49

#define N_PAD 50048   // N_NODES padded to multiple of 64 for wmma A-loads

// Scratch (allocation-free rule: __device__ globals)
__device__ __half g_buf0h[N_NODES * D];   // hop-1 output, fp16
__device__ __half g_buf1h[N_PAD * D];     // hop-2 output, fp16 (GEMM A)
__device__ __half g_Wh[D * D];            // W in fp16
__device__ int    g_cnt[N_NODES];
__device__ int    g_rank[N_EDGES];
__device__ int    g_rowptr[N_NODES + 1];
__device__ int    g_csr_src[N_EDGES];
__device__ float  g_norm[N_NODES];
__device__ int    g_blocksum[SCAN_NBLK];

// ---------------------------------------------------------------------------
// Degree histogram; atomic return value = this edge's rank within its dst.
// ---------------------------------------------------------------------------
__global__ void k_deg_rank(const int* __restrict__ dst) {
    int e = blockIdx.x * blockDim.x + threadIdx.x;
    if (e < N_EDGES) {
        g_rank[e] = atomicAdd(&g_cnt[dst[e]], 1);
    }
}

// ---------------------------------------------------------------------------
// Scan pass 1: per-block exclusive scan of g_cnt into g_rowptr, block totals.
// ---------------------------------------------------------------------------
__global__ void __launch_bounds__(SCAN_B) k_scan1() {
    __shared__ int sh[SCAN_B];
    int i = blockIdx.x * SCAN_B + threadIdx.x;
    int v = (i < N_NODES) ? g_cnt[i] : 0;
    sh[threadIdx.x] = v;
    __syncthreads();
#pragma unroll
    for (int off = 1; off < SCAN_B; off <<= 1) {
        int t = (threadIdx.x >= off) ? sh[threadIdx.x - off] : 0;
        __syncthreads();
        sh[threadIdx.x] += t;
        __syncthreads();
    }
    if (i < N_NODES) g_rowptr[i] = sh[threadIdx.x] - v;  // exclusive, local
    if (threadIdx.x == SCAN_B - 1) g_blocksum[blockIdx.x] = sh[SCAN_B - 1];
}

// ---------------------------------------------------------------------------
// Scan pass 2: block offsets via shared atomics, + norm, close rowptr.
// Also converts W to fp16 (blocks 49..56 handle 128x128 = 16384 elems).
// ---------------------------------------------------------------------------
__global__ void __launch_bounds__(SCAN_B) k_scan2(const float* __restrict__ W) {
    __shared__ int off;
    int t = threadIdx.x;
    if (t == 0) off = 0;
    __syncthreads();
    if (t < SCAN_NBLK && t < blockIdx.x) atomicAdd(&off, g_blocksum[t]);
    __syncthreads();
    int o = off;
    int i = blockIdx.x * SCAN_B + t;
    if (i < N_NODES) {
        g_rowptr[i] += o;
        g_norm[i] = rsqrtf(fmaxf((float)g_cnt[i], 1.0f));
    }
    if (i == 0) g_rowptr[N_NODES] = N_EDGES;
    // W fp32 -> fp16 (16384 elems), done by the first 16 blocks' threads
    int wi = blockIdx.x * SCAN_B + t;
    if (wi < D * D) g_Wh[wi] = __float2half(W[wi]);
}

// ---------------------------------------------------------------------------
// CSR fill: atomic-free scatter, 1 edge/thread (proven shape).
// ---------------------------------------------------------------------------
__global__ void k_fill(const int* __restrict__ src,
                       const int* __restrict__ dst) {
    int e = blockIdx.x * blockDim.x + threadIdx.x;
    if (e < N_EDGES) {
        int d = dst[e];
        g_csr_src[g_rowptr[d] + g_rank[e]] = src[e];
    }
}

// ---------------------------------------------------------------------------
// Hop 1: gather fp32 feat rows, write fp16.
// ---------------------------------------------------------------------------
__global__ void __launch_bounds__(256) k_hop1(const float* __restrict__ feat) {
    int w    = (blockIdx.x * blockDim.x + threadIdx.x) >> 5;
    int lane = threadIdx.x & 31;
    if (w >= N_NODES) return;

    int beg = g_rowptr[w];
    int end = g_rowptr[w + 1];
    float4 acc = make_float4(0.f, 0.f, 0.f, 0.f);
    const float4* in4 = (const float4*)feat;
    int e = beg;
    for (; e + 4 <= end; e += 4) {
        int s0 = __ldg(&g_csr_src[e + 0]), s1 = __ldg(&g_csr_src[e + 1]);
        int s2 = __ldg(&g_csr_src[e + 2]), s3 = __ldg(&g_csr_src[e + 3]);
        float n0 = __ldg(&g_norm[s0]), n1 = __ldg(&g_norm[s1]);
        float n2 = __ldg(&g_norm[s2]), n3 = __ldg(&g_norm[s3]);
        float4 v0 = __ldg(in4 + s0 * 32 + lane);
        float4 v1 = __ldg(in4 + s1 * 32 + lane);
        float4 v2 = __ldg(in4 + s2 * 32 + lane);
        float4 v3 = __ldg(in4 + s3 * 32 + lane);
        acc.x += n0 * v0.x + n1 * v1.x + n2 * v2.x + n3 * v3.x;
        acc.y += n0 * v0.y + n1 * v1.y + n2 * v2.y + n3 * v3.y;
        acc.z += n0 * v0.z + n1 * v1.z + n2 * v2.z + n3 * v3.z;
        acc.w += n0 * v0.w + n1 * v1.w + n2 * v2.w + n3 * v3.w;
    }
    for (; e < end; e++) {
        int s = __ldg(&g_csr_src[e]);
        float ns = __ldg(&g_norm[s]);
        float4 v = __ldg(in4 + s * 32 + lane);
        acc.x += ns * v.x; acc.y += ns * v.y;
        acc.z += ns * v.z; acc.w += ns * v.w;
    }
    float nd = g_norm[w];
    acc.x *= nd; acc.y *= nd; acc.z *= nd; acc.w *= nd;

    __half2 h0 = __floats2half2_rn(acc.x, acc.y);
    __half2 h1 = __floats2half2_rn(acc.z, acc.w);
    uint2 u;
    u.x = *(unsigned int*)&h0;
    u.y = *(unsigned int*)&h1;
    ((uint2*)g_buf0h)[w * 32 + lane] = u;
}

// ---------------------------------------------------------------------------
// Hop 2: gather fp16 rows, accumulate fp32, write fp16 (GEMM A operand).
// ---------------------------------------------------------------------------
__global__ void __launch_bounds__(256) k_hop2() {
    int w    = (blockIdx.x * blockDim.x + threadIdx.x) >> 5;
    int lane = threadIdx.x & 31;
    if (w >= N_NODES) return;

    int beg = g_rowptr[w];
    int end = g_rowptr[w + 1];
    float4 acc = make_float4(0.f, 0.f, 0.f, 0.f);
    const uint2* in2 = (const uint2*)g_buf0h;
    int e = beg;
    for (; e + 4 <= end; e += 4) {
        int s0 = __ldg(&g_csr_src[e + 0]), s1 = __ldg(&g_csr_src[e + 1]);
        int s2 = __ldg(&g_csr_src[e + 2]), s3 = __ldg(&g_csr_src[e + 3]);
        float n0 = __ldg(&g_norm[s0]), n1 = __ldg(&g_norm[s1]);
        float n2 = __ldg(&g_norm[s2]), n3 = __ldg(&g_norm[s3]);
        uint2 u0 = __ldg(in2 + s0 * 32 + lane);
        uint2 u1 = __ldg(in2 + s1 * 32 + lane);
        uint2 u2 = __ldg(in2 + s2 * 32 + lane);
        uint2 u3 = __ldg(in2 + s3 * 32 + lane);
        float2 a0 = __half22float2(*(__half2*)&u0.x), b0 = __half22float2(*(__half2*)&u0.y);
        float2 a1 = __half22float2(*(__half2*)&u1.x), b1 = __half22float2(*(__half2*)&u1.y);
        float2 a2 = __half22float2(*(__half2*)&u2.x), b2 = __half22float2(*(__half2*)&u2.y);
        float2 a3 = __half22float2(*(__half2*)&u3.x), b3 = __half22float2(*(__half2*)&u3.y);
        acc.x += n0 * a0.x + n1 * a1.x + n2 * a2.x + n3 * a3.x;
        acc.y += n0 * a0.y + n1 * a1.y + n2 * a2.y + n3 * a3.y;
        acc.z += n0 * b0.x + n1 * b1.x + n2 * b2.x + n3 * b3.x;
        acc.w += n0 * b0.y + n1 * b1.y + n2 * b2.y + n3 * b3.y;
    }
    for (; e < end; e++) {
        int s = __ldg(&g_csr_src[e]);
        float ns = __ldg(&g_norm[s]);
        uint2 u = __ldg(in2 + s * 32 + lane);
        float2 a = __half22float2(*(__half2*)&u.x);
        float2 b = __half22float2(*(__half2*)&u.y);
        acc.x += ns * a.x; acc.y += ns * a.y;
        acc.z += ns * b.x; acc.w += ns * b.y;
    }
    float nd = g_norm[w];
    acc.x *= nd; acc.y *= nd; acc.z *= nd; acc.w *= nd;

    __half2 h0 = __floats2half2_rn(acc.x, acc.y);
    __half2 h1 = __floats2half2_rn(acc.z, acc.w);
    uint2 u;
    u.x = *(unsigned int*)&h0;
    u.y = *(unsigned int*)&h1;
    ((uint2*)g_buf1h)[w * 32 + lane] = u;
}

// ---------------------------------------------------------------------------
// Zero the pad rows of g_buf1h (rows N_NODES..N_PAD-1) so wmma A-loads of the
// tail block read clean data.
// ---------------------------------------------------------------------------
__global__ void k_padzero() {
    int i = blockIdx.x * blockDim.x + threadIdx.x;
    const int padElems = (N_PAD - N_NODES) * D / 4;   // 48*128/4 = 1536 uint2
    if (i < padElems) {
        ((uint2*)(g_buf1h + N_NODES * D))[i] = make_uint2(0u, 0u);
    }
}

// ---------------------------------------------------------------------------
// Tensor-core GEMM: out[n][o] = sum_k A[n][k] * W[o][k] + b[o]
// A = g_buf1h fp16 row-major [N_PAD,128]; B = W^T = g_Wh read col-major.
// Block: 256 thr = 8 warps (4 M x 2 N); block tile 64x128; warp tile 16x64.
// Accumulator initialized from a bias tile in smem (bias folded in).
// 50000 % 16 == 0, so the per-16-row store guard is exact.
// ---------------------------------------------------------------------------
#define GBM 64
__global__ void __launch_bounds__(256) k_gemm(const float* __restrict__ bias,
                                              float* __restrict__ out) {
    __shared__ float sbias[16][128];   // 16 identical rows of bias

    int t = threadIdx.x;
    // build bias tile: 16*128 = 2048 floats, 8 per thread
#pragma unroll
    for (int i = 0; i < 8; i++) {
        int idx = t + i * 256;
        sbias[idx >> 7][idx & 127] = bias[idx & 127];
    }
    __syncthreads();

    int warp = t >> 5;
    int wm = warp >> 1;          // 0..3
    int wn = warp & 1;           // 0..1
    int row0 = blockIdx.x * GBM + wm * 16;
    int col0 = wn * 64;

    wmma::fragment<wmma::accumulator, 16, 16, 16, float> acc[4];
#pragma unroll
    for (int j = 0; j < 4; j++)
        wmma::load_matrix_sync(acc[j], &sbias[0][col0 + j * 16], 128,
                               wmma::mem_row_major);

#pragma unroll
    for (int k0 = 0; k0 < D; k0 += 16) {
        wmma::fragment<wmma::matrix_a, 16, 16, 16, __half, wmma::row_major> a;
        wmma::load_matrix_sync(a, g_buf1h + (size_t)row0 * D + k0, D);
#pragma unroll
        for (int j = 0; j < 4; j++) {
            wmma::fragment<wmma::matrix_b, 16, 16, 16, __half, wmma::col_major> b;
            // B(k, o) = W[o][k]: col-major with ld=D
            wmma::load_matrix_sync(b, g_Wh + (size_t)(col0 + j * 16) * D + k0, D);
            wmma::mma_sync(acc[j], a, b, acc[j]);
        }
    }

    if (row0 + 16 <= N_NODES) {
#pragma unroll
        for (int j = 0; j < 4; j++)
            wmma::store_matrix_sync(out + (size_t)row0 * D + col0 + j * 16,
                                    acc[j], D, wmma::mem_row_major);
    }
}

// ---------------------------------------------------------------------------
// kernel_launch
// ---------------------------------------------------------------------------
extern "C" void kernel_launch(void* const* d_in, const int* in_sizes, int n_in,
                              void* d_out, int out_size) {
    const float* feat = (const float*)d_in[0];
    const int*   src  = (const int*)d_in[1];
    const int*   dst  = (const int*)d_in[2];
    const float* W    = (const float*)d_in[3];
    const float* bias = (const float*)d_in[4];
    float*       out  = (float*)d_out;

    const int gEdge = (N_EDGES + 255) / 256;
    const int gHop  = (N_NODES * 32 + 255) / 256;   // warp per node
    const int gGemm = (N_PAD + GBM - 1) / GBM;      // 782

    void* p = nullptr;
    cudaGetSymbolAddress(&p, g_cnt);
    cudaMemsetAsync(p, 0, N_NODES * sizeof(int), 0);

    k_deg_rank<<<gEdge, 256>>>(dst);
    k_scan1   <<<SCAN_NBLK, SCAN_B>>>();
    k_scan2   <<<SCAN_NBLK, SCAN_B>>>(W);
    k_fill    <<<gEdge, 256>>>(src, dst);
    k_padzero <<<8, 256>>>();
    k_hop1    <<<gHop, 256>>>(feat);    // feat (fp32) -> g_buf0h (fp16)
    k_hop2    <<<gHop, 256>>>();        // g_buf0h     -> g_buf1h (fp16)
    k_gemm    <<<gGemm, 256>>>(bias, out);
}

// round 12
// speedup vs baseline: 1.8375x; 1.1050x over previous
#include <cuda_runtime.h>
#include <cuda_fp16.h>
#include <mma.h>

using namespace nvcuda;

#define N_NODES 50000
#define N_EDGES 1600000
#define D 128

#define SCAN_B 1024
#define SCAN_NBLK ((N_NODES + SCAN_B - 1) / SCAN_B)   // 49

#define N_PAD 50048   // N_NODES padded to multiple of 64 for wmma A-loads

// Scratch (allocation-free rule: __device__ globals)
__device__ __half g_feath[N_NODES * D];   // fp16 copy of input features
__device__ __half g_buf0h[N_NODES * D];   // hop-1 output, fp16
__device__ __half g_buf1h[N_PAD * D];     // hop-2 output, fp16 (GEMM A)
__device__ __half g_Wh[D * D];            // W in fp16
__device__ int    g_cnt[N_NODES];
__device__ int    g_rank[N_EDGES];
__device__ int    g_rowptr[N_NODES + 1];
__device__ int    g_csr_src[N_EDGES];
__device__ float  g_norm[N_NODES];
__device__ int    g_blocksum[SCAN_NBLK];

// ---------------------------------------------------------------------------
// Degree histogram + per-edge rank; ALSO converts feat fp32->fp16.
// 1.6M threads x 4 floats == N_NODES*D elements exactly; the coalesced copy
// hides under the scattered atomic's latency (kernel is issue-starved).
// ---------------------------------------------------------------------------
__global__ void k_deg_rank_cvt(const int* __restrict__ dst,
                               const float* __restrict__ feat) {
    int e = blockIdx.x * blockDim.x + threadIdx.x;
    if (e < N_EDGES) {
        g_rank[e] = atomicAdd(&g_cnt[dst[e]], 1);
        float4 v = ((const float4*)feat)[e];
        __half2 h0 = __floats2half2_rn(v.x, v.y);
        __half2 h1 = __floats2half2_rn(v.z, v.w);
        uint2 u;
        u.x = *(unsigned int*)&h0;
        u.y = *(unsigned int*)&h1;
        ((uint2*)g_feath)[e] = u;
    }
}

// ---------------------------------------------------------------------------
// Scan pass 1: per-block exclusive scan of g_cnt into g_rowptr, block totals.
// ---------------------------------------------------------------------------
__global__ void __launch_bounds__(SCAN_B) k_scan1() {
    __shared__ int sh[SCAN_B];
    int i = blockIdx.x * SCAN_B + threadIdx.x;
    int v = (i < N_NODES) ? g_cnt[i] : 0;
    sh[threadIdx.x] = v;
    __syncthreads();
#pragma unroll
    for (int off = 1; off < SCAN_B; off <<= 1) {
        int t = (threadIdx.x >= off) ? sh[threadIdx.x - off] : 0;
        __syncthreads();
        sh[threadIdx.x] += t;
        __syncthreads();
    }
    if (i < N_NODES) g_rowptr[i] = sh[threadIdx.x] - v;  // exclusive, local
    if (threadIdx.x == SCAN_B - 1) g_blocksum[blockIdx.x] = sh[SCAN_B - 1];
}

// ---------------------------------------------------------------------------
// Scan pass 2: block offsets via shared atomics, + norm, close rowptr.
// Also converts W to fp16 (first 16 blocks cover 128x128 elems).
// ---------------------------------------------------------------------------
__global__ void __launch_bounds__(SCAN_B) k_scan2(const float* __restrict__ W) {
    __shared__ int off;
    int t = threadIdx.x;
    if (t == 0) off = 0;
    __syncthreads();
    if (t < SCAN_NBLK && t < blockIdx.x) atomicAdd(&off, g_blocksum[t]);
    __syncthreads();
    int o = off;
    int i = blockIdx.x * SCAN_B + t;
    if (i < N_NODES) {
        g_rowptr[i] += o;
        g_norm[i] = rsqrtf(fmaxf((float)g_cnt[i], 1.0f));
    }
    if (i == 0) g_rowptr[N_NODES] = N_EDGES;
    int wi = blockIdx.x * SCAN_B + t;
    if (wi < D * D) g_Wh[wi] = __float2half(W[wi]);
}

// ---------------------------------------------------------------------------
// CSR fill: atomic-free scatter (proven shape); also zeroes GEMM A pad rows.
// ---------------------------------------------------------------------------
__global__ void k_fill(const int* __restrict__ src,
                       const int* __restrict__ dst) {
    int e = blockIdx.x * blockDim.x + threadIdx.x;
    if (e < N_EDGES) {
        int d = dst[e];
        g_csr_src[g_rowptr[d] + g_rank[e]] = src[e];
    }
    // pad rows N_NODES..N_PAD-1 of g_buf1h: 48*128 halves = 1536 uint2
    if (e < (N_PAD - N_NODES) * D / 4) {
        ((uint2*)(g_buf1h + N_NODES * D))[e] = make_uint2(0u, 0u);
    }
}

// ---------------------------------------------------------------------------
// Pull-mode hop, HALF-WARP per dst node. fp16 rows are 256 B = 16 lanes x
// uint4, so 16 lanes cover a row: 2x node parallelism, 2x rows in flight,
// and the degree-imbalance tail averages over 16 units/block instead of 8.
//   out[d] = norm[d] * sum_{s in N(d)} norm[s] * in[s]
// HOP=1: in = g_feath, out = g_buf0h.  HOP=2: in = g_buf0h, out = g_buf1h.
// ---------------------------------------------------------------------------
template <int HOP>
__global__ void __launch_bounds__(256) k_hop() {
    int hw   = (blockIdx.x * blockDim.x + threadIdx.x) >> 4;   // node id
    int lane = threadIdx.x & 15;
    if (hw >= N_NODES) return;

    const uint4* in4 = (const uint4*)((HOP == 1) ? g_feath : g_buf0h);

    int beg = g_rowptr[hw];
    int end = g_rowptr[hw + 1];
    float acc[8] = {0.f, 0.f, 0.f, 0.f, 0.f, 0.f, 0.f, 0.f};

#define ACC_U4(u, n)                                                  \
    do {                                                              \
        __half2* _h = (__half2*)&(u);                                 \
        float2 _f0 = __half22float2(_h[0]);                           \
        float2 _f1 = __half22float2(_h[1]);                           \
        float2 _f2 = __half22float2(_h[2]);                           \
        float2 _f3 = __half22float2(_h[3]);                           \
        acc[0] += (n) * _f0.x; acc[1] += (n) * _f0.y;                 \
        acc[2] += (n) * _f1.x; acc[3] += (n) * _f1.y;                 \
        acc[4] += (n) * _f2.x; acc[5] += (n) * _f2.y;                 \
        acc[6] += (n) * _f3.x; acc[7] += (n) * _f3.y;                 \
    } while (0)

    int e = beg;
    for (; e + 4 <= end; e += 4) {
        int s0 = __ldg(&g_csr_src[e + 0]), s1 = __ldg(&g_csr_src[e + 1]);
        int s2 = __ldg(&g_csr_src[e + 2]), s3 = __ldg(&g_csr_src[e + 3]);
        float n0 = __ldg(&g_norm[s0]), n1 = __ldg(&g_norm[s1]);
        float n2 = __ldg(&g_norm[s2]), n3 = __ldg(&g_norm[s3]);
        uint4 u0 = __ldg(in4 + s0 * 16 + lane);
        uint4 u1 = __ldg(in4 + s1 * 16 + lane);
        uint4 u2 = __ldg(in4 + s2 * 16 + lane);
        uint4 u3 = __ldg(in4 + s3 * 16 + lane);
        ACC_U4(u0, n0);
        ACC_U4(u1, n1);
        ACC_U4(u2, n2);
        ACC_U4(u3, n3);
    }
    for (; e < end; e++) {
        int s = __ldg(&g_csr_src[e]);
        float ns = __ldg(&g_norm[s]);
        uint4 u = __ldg(in4 + s * 16 + lane);
        ACC_U4(u, ns);
    }
#undef ACC_U4

    float nd = g_norm[hw];
#pragma unroll
    for (int j = 0; j < 8; j++) acc[j] *= nd;

    __half2 h0 = __floats2half2_rn(acc[0], acc[1]);
    __half2 h1 = __floats2half2_rn(acc[2], acc[3]);
    __half2 h2 = __floats2half2_rn(acc[4], acc[5]);
    __half2 h3 = __floats2half2_rn(acc[6], acc[7]);
    uint4 u;
    u.x = *(unsigned int*)&h0;
    u.y = *(unsigned int*)&h1;
    u.z = *(unsigned int*)&h2;
    u.w = *(unsigned int*)&h3;
    __half* outp = (HOP == 1) ? g_buf0h : g_buf1h;
    ((uint4*)outp)[hw * 16 + lane] = u;
}

// ---------------------------------------------------------------------------
// Tensor-core GEMM: out[n][o] = sum_k A[n][k] * W[o][k] + b[o]
// A = g_buf1h fp16 row-major; B = g_Wh read col-major (B(k,o)=W[o][k]).
// 256 thr = 8 warps (4 M x 2 N); block tile 64x128; warp tile 16x64.
// Bias folded in via smem-initialized accumulators. (R11-proven, ~10us.)
// ---------------------------------------------------------------------------
#define GBM 64
__global__ void __launch_bounds__(256) k_gemm(const float* __restrict__ bias,
                                              float* __restrict__ out) {
    __shared__ float sbias[16][128];

    int t = threadIdx.x;
#pragma unroll
    for (int i = 0; i < 8; i++) {
        int idx = t + i * 256;
        sbias[idx >> 7][idx & 127] = bias[idx & 127];
    }
    __syncthreads();

    int warp = t >> 5;
    int wm = warp >> 1;
    int wn = warp & 1;
    int row0 = blockIdx.x * GBM + wm * 16;
    int col0 = wn * 64;

    wmma::fragment<wmma::accumulator, 16, 16, 16, float> acc[4];
#pragma unroll
    for (int j = 0; j < 4; j++)
        wmma::load_matrix_sync(acc[j], &sbias[0][col0 + j * 16], 128,
                               wmma::mem_row_major);

#pragma unroll
    for (int k0 = 0; k0 < D; k0 += 16) {
        wmma::fragment<wmma::matrix_a, 16, 16, 16, __half, wmma::row_major> a;
        wmma::load_matrix_sync(a, g_buf1h + (size_t)row0 * D + k0, D);
#pragma unroll
        for (int j = 0; j < 4; j++) {
            wmma::fragment<wmma::matrix_b, 16, 16, 16, __half, wmma::col_major> b;
            wmma::load_matrix_sync(b, g_Wh + (size_t)(col0 + j * 16) * D + k0, D);
            wmma::mma_sync(acc[j], a, b, acc[j]);
        }
    }

    if (row0 + 16 <= N_NODES) {
#pragma unroll
        for (int j = 0; j < 4; j++)
            wmma::store_matrix_sync(out + (size_t)row0 * D + col0 + j * 16,
                                    acc[j], D, wmma::mem_row_major);
    }
}

// ---------------------------------------------------------------------------
// kernel_launch
// ---------------------------------------------------------------------------
extern "C" void kernel_launch(void* const* d_in, const int* in_sizes, int n_in,
                              void* d_out, int out_size) {
    const float* feat = (const float*)d_in[0];
    const int*   src  = (const int*)d_in[1];
    const int*   dst  = (const int*)d_in[2];
    const float* W    = (const float*)d_in[3];
    const float* bias = (const float*)d_in[4];
    float*       out  = (float*)d_out;

    const int gEdge = (N_EDGES + 255) / 256;
    const int gHop  = (N_NODES * 16 + 255) / 256;   // half-warp per node: 3125
    const int gGemm = (N_PAD + GBM - 1) / GBM;      // 782

    void* p = nullptr;
    cudaGetSymbolAddress(&p, g_cnt);
    cudaMemsetAsync(p, 0, N_NODES * sizeof(int), 0);

    k_deg_rank_cvt<<<gEdge, 256>>>(dst, feat);   // histogram + feat->fp16
    k_scan1       <<<SCAN_NBLK, SCAN_B>>>();
    k_scan2       <<<SCAN_NBLK, SCAN_B>>>(W);    // offsets + norm + W->fp16
    k_fill        <<<gEdge, 256>>>(src, dst);    // CSR + pad-zero
    k_hop<1>      <<<gHop, 256>>>();             // g_feath -> g_buf0h
    k_hop<2>      <<<gHop, 256>>>();             // g_buf0h -> g_buf1h
    k_gemm        <<<gGemm, 256>>>(bias, out);
}

// round 13
// speedup vs baseline: 2.0129x; 1.0954x over previous
#include <cuda_runtime.h>
#include <cuda_fp16.h>
#include <mma.h>

using namespace nvcuda;

#define N_NODES 50000
#define N_EDGES 1600000
#define D 128

#define SCAN_B 1024
#define SCAN_NBLK ((N_NODES + SCAN_B - 1) / SCAN_B)   // 49

#define N_PAD 50048   // N_NODES padded to multiple of 64 for wmma A-loads

// Scratch (allocation-free rule: __device__ globals)
__device__ __half g_feath[N_NODES * D];   // norm[s]*feat[s], fp16
__device__ __half g_buf0h[N_NODES * D];   // norm[d]^2 * hop1-sum, fp16
__device__ __half g_buf1h[N_PAD * D];     // final hop2 output, fp16 (GEMM A)
__device__ __half g_Wh[D * D];            // W in fp16
__device__ int    g_cnt[N_NODES];
__device__ int    g_rank[N_EDGES];
__device__ int    g_rowptr[N_NODES + 1];
__device__ int    g_csr_src[N_EDGES];
__device__ float  g_norm[N_NODES];
__device__ int    g_blocksum[SCAN_NBLK];

// ---------------------------------------------------------------------------
// Degree histogram; atomic return value = this edge's rank within its dst.
// (Proven shape, ~16us.)
// ---------------------------------------------------------------------------
__global__ void k_deg_rank(const int* __restrict__ dst) {
    int e = blockIdx.x * blockDim.x + threadIdx.x;
    if (e < N_EDGES) {
        g_rank[e] = atomicAdd(&g_cnt[dst[e]], 1);
    }
}

// ---------------------------------------------------------------------------
// Scan pass 1: per-block exclusive scan of g_cnt into g_rowptr, block totals.
// ---------------------------------------------------------------------------
__global__ void __launch_bounds__(SCAN_B) k_scan1() {
    __shared__ int sh[SCAN_B];
    int i = blockIdx.x * SCAN_B + threadIdx.x;
    int v = (i < N_NODES) ? g_cnt[i] : 0;
    sh[threadIdx.x] = v;
    __syncthreads();
#pragma unroll
    for (int off = 1; off < SCAN_B; off <<= 1) {
        int t = (threadIdx.x >= off) ? sh[threadIdx.x - off] : 0;
        __syncthreads();
        sh[threadIdx.x] += t;
        __syncthreads();
    }
    if (i < N_NODES) g_rowptr[i] = sh[threadIdx.x] - v;  // exclusive, local
    if (threadIdx.x == SCAN_B - 1) g_blocksum[blockIdx.x] = sh[SCAN_B - 1];
}

// ---------------------------------------------------------------------------
// Scan pass 2: block offsets via shared atomics, + norm, close rowptr.
// Also converts W to fp16 (first 16 blocks cover 128x128 elems).
// ---------------------------------------------------------------------------
__global__ void __launch_bounds__(SCAN_B) k_scan2(const float* __restrict__ W) {
    __shared__ int off;
    int t = threadIdx.x;
    if (t == 0) off = 0;
    __syncthreads();
    if (t < SCAN_NBLK && t < blockIdx.x) atomicAdd(&off, g_blocksum[t]);
    __syncthreads();
    int o = off;
    int i = blockIdx.x * SCAN_B + t;
    if (i < N_NODES) {
        g_rowptr[i] += o;
        g_norm[i] = rsqrtf(fmaxf((float)g_cnt[i], 1.0f));
    }
    if (i == 0) g_rowptr[N_NODES] = N_EDGES;
    int wi = blockIdx.x * SCAN_B + t;
    if (wi < D * D) g_Wh[wi] = __float2half(W[wi]);
}

// ---------------------------------------------------------------------------
// CSR fill + feat conversion pre-scaled by norm[row] + GEMM pad-zero.
// The coalesced cvt work hides under the scatter's latency (issue ~8%).
// 1.6M threads x 4 floats == N_NODES*D exactly.
// ---------------------------------------------------------------------------
__global__ void k_fill_cvt(const int* __restrict__ src,
                           const int* __restrict__ dst,
                           const float* __restrict__ feat) {
    int e = blockIdx.x * blockDim.x + threadIdx.x;
    if (e < N_EDGES) {
        int d = dst[e];
        g_csr_src[g_rowptr[d] + g_rank[e]] = src[e];

        // feat' = norm[row] * feat, fp16 (element group e = floats [4e,4e+4))
        int row = e >> 5;                    // 32 float4-groups per row
        float nm = g_norm[row];
        float4 v = ((const float4*)feat)[e];
        __half2 h0 = __floats2half2_rn(nm * v.x, nm * v.y);
        __half2 h1 = __floats2half2_rn(nm * v.z, nm * v.w);
        uint2 u;
        u.x = *(unsigned int*)&h0;
        u.y = *(unsigned int*)&h1;
        ((uint2*)g_feath)[e] = u;
    }
    // pad rows N_NODES..N_PAD-1 of g_buf1h: 48*128 halves = 1536 uint2
    if (e < (N_PAD - N_NODES) * D / 4) {
        ((uint2*)(g_buf1h + N_NODES * D))[e] = make_uint2(0u, 0u);
    }
}

// ---------------------------------------------------------------------------
// Pull-mode hop, half-warp per dst node, norm-free inner loop:
//   HOP=1: buf0h[d] = norm[d]^2 * sum_{s in N(d)} feath[s]
//   HOP=2: buf1h[d] = norm[d]   * sum_{s in N(d)} buf0h[s]
// Inner loop per edge: 1 coalesced index load + 1 row gather. fp32 accum.
// ---------------------------------------------------------------------------
template <int HOP>
__global__ void __launch_bounds__(256) k_hop() {
    int hw   = (blockIdx.x * blockDim.x + threadIdx.x) >> 4;   // node id
    int lane = threadIdx.x & 15;
    if (hw >= N_NODES) return;

    const uint4* in4 = (const uint4*)((HOP == 1) ? g_feath : g_buf0h);

    int beg = g_rowptr[hw];
    int end = g_rowptr[hw + 1];
    float acc[8] = {0.f, 0.f, 0.f, 0.f, 0.f, 0.f, 0.f, 0.f};

#define ACC_U4(u)                                                     \
    do {                                                              \
        __half2* _h = (__half2*)&(u);                                 \
        float2 _f0 = __half22float2(_h[0]);                           \
        float2 _f1 = __half22float2(_h[1]);                           \
        float2 _f2 = __half22float2(_h[2]);                           \
        float2 _f3 = __half22float2(_h[3]);                           \
        acc[0] += _f0.x; acc[1] += _f0.y;                             \
        acc[2] += _f1.x; acc[3] += _f1.y;                             \
        acc[4] += _f2.x; acc[5] += _f2.y;                             \
        acc[6] += _f3.x; acc[7] += _f3.y;                             \
    } while (0)

    int e = beg;
    for (; e + 4 <= end; e += 4) {
        int s0 = __ldg(&g_csr_src[e + 0]), s1 = __ldg(&g_csr_src[e + 1]);
        int s2 = __ldg(&g_csr_src[e + 2]), s3 = __ldg(&g_csr_src[e + 3]);
        uint4 u0 = __ldg(in4 + s0 * 16 + lane);
        uint4 u1 = __ldg(in4 + s1 * 16 + lane);
        uint4 u2 = __ldg(in4 + s2 * 16 + lane);
        uint4 u3 = __ldg(in4 + s3 * 16 + lane);
        ACC_U4(u0);
        ACC_U4(u1);
        ACC_U4(u2);
        ACC_U4(u3);
    }
    for (; e < end; e++) {
        int s = __ldg(&g_csr_src[e]);
        uint4 u = __ldg(in4 + s * 16 + lane);
        ACC_U4(u);
    }
#undef ACC_U4

    float nd = g_norm[hw];
    float scale = (HOP == 1) ? nd * nd : nd;
#pragma unroll
    for (int j = 0; j < 8; j++) acc[j] *= scale;

    __half2 h0 = __floats2half2_rn(acc[0], acc[1]);
    __half2 h1 = __floats2half2_rn(acc[2], acc[3]);
    __half2 h2 = __floats2half2_rn(acc[4], acc[5]);
    __half2 h3 = __floats2half2_rn(acc[6], acc[7]);
    uint4 u;
    u.x = *(unsigned int*)&h0;
    u.y = *(unsigned int*)&h1;
    u.z = *(unsigned int*)&h2;
    u.w = *(unsigned int*)&h3;
    __half* outp = (HOP == 1) ? g_buf0h : g_buf1h;
    ((uint4*)outp)[hw * 16 + lane] = u;
}

// ---------------------------------------------------------------------------
// Tensor-core GEMM: out[n][o] = sum_k A[n][k] * W[o][k] + b[o]
// (R11-proven, ~10us.)
// ---------------------------------------------------------------------------
#define GBM 64
__global__ void __launch_bounds__(256) k_gemm(const float* __restrict__ bias,
                                              float* __restrict__ out) {
    __shared__ float sbias[16][128];

    int t = threadIdx.x;
#pragma unroll
    for (int i = 0; i < 8; i++) {
        int idx = t + i * 256;
        sbias[idx >> 7][idx & 127] = bias[idx & 127];
    }
    __syncthreads();

    int warp = t >> 5;
    int wm = warp >> 1;
    int wn = warp & 1;
    int row0 = blockIdx.x * GBM + wm * 16;
    int col0 = wn * 64;

    wmma::fragment<wmma::accumulator, 16, 16, 16, float> acc[4];
#pragma unroll
    for (int j = 0; j < 4; j++)
        wmma::load_matrix_sync(acc[j], &sbias[0][col0 + j * 16], 128,
                               wmma::mem_row_major);

#pragma unroll
    for (int k0 = 0; k0 < D; k0 += 16) {
        wmma::fragment<wmma::matrix_a, 16, 16, 16, __half, wmma::row_major> a;
        wmma::load_matrix_sync(a, g_buf1h + (size_t)row0 * D + k0, D);
#pragma unroll
        for (int j = 0; j < 4; j++) {
            wmma::fragment<wmma::matrix_b, 16, 16, 16, __half, wmma::col_major> b;
            wmma::load_matrix_sync(b, g_Wh + (size_t)(col0 + j * 16) * D + k0, D);
            wmma::mma_sync(acc[j], a, b, acc[j]);
        }
    }

    if (row0 + 16 <= N_NODES) {
#pragma unroll
        for (int j = 0; j < 4; j++)
            wmma::store_matrix_sync(out + (size_t)row0 * D + col0 + j * 16,
                                    acc[j], D, wmma::mem_row_major);
    }
}

// ---------------------------------------------------------------------------
// kernel_launch
// ---------------------------------------------------------------------------
extern "C" void kernel_launch(void* const* d_in, const int* in_sizes, int n_in,
                              void* d_out, int out_size) {
    const float* feat = (const float*)d_in[0];
    const int*   src  = (const int*)d_in[1];
    const int*   dst  = (const int*)d_in[2];
    const float* W    = (const float*)d_in[3];
    const float* bias = (const float*)d_in[4];
    float*       out  = (float*)d_out;

    const int gEdge = (N_EDGES + 255) / 256;
    const int gHop  = (N_NODES * 16 + 255) / 256;   // half-warp per node
    const int gGemm = (N_PAD + GBM - 1) / GBM;      // 782

    void* p = nullptr;
    cudaGetSymbolAddress(&p, g_cnt);
    cudaMemsetAsync(p, 0, N_NODES * sizeof(int), 0);

    k_deg_rank<<<gEdge, 256>>>(dst);
    k_scan1   <<<SCAN_NBLK, SCAN_B>>>();
    k_scan2   <<<SCAN_NBLK, SCAN_B>>>(W);        // offsets + norm + W->fp16
    k_fill_cvt<<<gEdge, 256>>>(src, dst, feat);  // CSR + feat'*norm fp16 + pad
    k_hop<1>  <<<gHop, 256>>>();                 // g_feath -> g_buf0h
    k_hop<2>  <<<gHop, 256>>>();                 // g_buf0h -> g_buf1h
    k_gemm    <<<gGemm, 256>>>(bias, out);
}

// round 14
// speedup vs baseline: 2.0187x; 1.0029x over previous
#include <cuda_runtime.h>
#include <cuda_fp16.h>
#include <mma.h>

using namespace nvcuda;

#define N_NODES 50000
#define N_EDGES 1600000
#define D 128

#define SCAN_B 256
#define SCAN_NBLK ((N_NODES + SCAN_B - 1) / SCAN_B)   // 196

#define N_PAD 50048   // N_NODES padded to multiple of 64 for wmma A-loads

// Scratch (allocation-free rule: __device__ globals)
__device__ __half g_feath[N_NODES * D];   // norm[s]*feat[s], fp16
__device__ __half g_buf0h[N_NODES * D];   // norm[d]^2 * hop1-sum, fp16
__device__ __half g_buf1h[N_PAD * D];     // final hop2 output, fp16 (GEMM A)
__device__ __half g_Wh[D * D];            // W in fp16
__device__ int    g_cnt[N_NODES];
__device__ unsigned short g_rank[N_EDGES];  // coalesced u16 (rank < 65536)
__device__ int    g_rowptr[N_NODES + 1];
__device__ int    g_csr_src[N_EDGES];
__device__ float  g_norm[N_NODES];
__device__ int    g_blocksum[SCAN_NBLK];

// ---------------------------------------------------------------------------
// Degree histogram; atomic return value = this edge's rank within its dst.
// rank stored u16 (coalesced store, safe).
// ---------------------------------------------------------------------------
__global__ void k_deg_rank(const int* __restrict__ dst) {
    int e = blockIdx.x * blockDim.x + threadIdx.x;
    if (e < N_EDGES) {
        g_rank[e] = (unsigned short)atomicAdd(&g_cnt[dst[e]], 1);
    }
}

// ---------------------------------------------------------------------------
// Scan pass 1: per-block (256-wide) exclusive scan of g_cnt, block totals.
// 196 blocks -> much better latency hiding than 49x1024.
// ---------------------------------------------------------------------------
__global__ void __launch_bounds__(SCAN_B) k_scan1() {
    __shared__ int warp_sums[8];
    int i = blockIdx.x * SCAN_B + threadIdx.x;
    int v = (i < N_NODES) ? g_cnt[i] : 0;

    int lane = threadIdx.x & 31;
    int wid  = threadIdx.x >> 5;
    int s = v;
#pragma unroll
    for (int off = 1; off < 32; off <<= 1) {
        int u = __shfl_up_sync(0xffffffffu, s, off);
        if (lane >= off) s += u;
    }
    if (lane == 31) warp_sums[wid] = s;
    __syncthreads();
    if (wid == 0 && lane < 8) {
        int w = warp_sums[lane];
        int wv = w;
#pragma unroll
        for (int off = 1; off < 8; off <<= 1) {
            int u = __shfl_up_sync(0xffu, wv, off);
            if (lane >= off) wv += u;
        }
        warp_sums[lane] = wv - w;   // exclusive warp offsets
    }
    __syncthreads();
    int incl = s + warp_sums[wid];
    if (i < N_NODES) g_rowptr[i] = incl - v;   // exclusive, local
    if (threadIdx.x == SCAN_B - 1) g_blocksum[blockIdx.x] = incl;
}

// ---------------------------------------------------------------------------
// Scan pass 2: block offsets via shared atomics, + norm, close rowptr.
// Also converts W to fp16 (first 64 blocks cover 128x128 elems).
// ---------------------------------------------------------------------------
__global__ void __launch_bounds__(SCAN_B) k_scan2(const float* __restrict__ W) {
    __shared__ int off;
    int t = threadIdx.x;
    if (t == 0) off = 0;
    __syncthreads();
    for (int b = t; b < blockIdx.x; b += SCAN_B) {
        atomicAdd(&off, g_blocksum[b]);
    }
    __syncthreads();
    int o = off;
    int i = blockIdx.x * SCAN_B + t;
    if (i < N_NODES) {
        g_rowptr[i] += o;
        g_norm[i] = rsqrtf(fmaxf((float)g_cnt[i], 1.0f));
    }
    if (i == 0) g_rowptr[N_NODES] = N_EDGES;
    int wi = blockIdx.x * SCAN_B + t;
    if (wi < D * D) g_Wh[wi] = __float2half(W[wi]);
}

// ---------------------------------------------------------------------------
// CSR fill + feat'=norm*feat fp16 conversion + GEMM pad-zero.
// 2 edges per thread (split halves: e, e+N/2) -> 2 independent scatter chains,
// no tail branch. 800k threads x 2 float4 groups covers N_NODES*D exactly.
// ---------------------------------------------------------------------------
#define FILL_T (N_EDGES / 2)   // 800000
__global__ void k_fill_cvt(const int* __restrict__ src,
                           const int* __restrict__ dst,
                           const float* __restrict__ feat) {
    int i = blockIdx.x * blockDim.x + threadIdx.x;
    if (i >= FILL_T) return;
    int e0 = i;
    int e1 = i + FILL_T;

    int d0 = dst[e0], d1 = dst[e1];
    int s0 = src[e0], s1 = src[e1];
    int r0 = g_rank[e0], r1 = g_rank[e1];
    int p0 = g_rowptr[d0], p1 = g_rowptr[d1];
    g_csr_src[p0 + r0] = s0;
    g_csr_src[p1 + r1] = s1;

#pragma unroll
    for (int h = 0; h < 2; h++) {
        int e = i + h * FILL_T;          // float4-group index
        int row = e >> 5;                // 32 groups per row
        float nm = g_norm[row];
        float4 v = ((const float4*)feat)[e];
        __half2 h0 = __floats2half2_rn(nm * v.x, nm * v.y);
        __half2 h1 = __floats2half2_rn(nm * v.z, nm * v.w);
        uint2 u;
        u.x = *(unsigned int*)&h0;
        u.y = *(unsigned int*)&h1;
        ((uint2*)g_feath)[e] = u;
    }
    // pad rows N_NODES..N_PAD-1 of g_buf1h: 48*128 halves = 1536 uint2
    if (i < (N_PAD - N_NODES) * D / 4) {
        ((uint2*)(g_buf1h + N_NODES * D))[i] = make_uint2(0u, 0u);
    }
}

// ---------------------------------------------------------------------------
// Pull-mode hop, half-warp per dst node, norm-free inner loop:
//   HOP=1: buf0h[d] = norm[d]^2 * sum_{s in N(d)} feath[s]
//   HOP=2: buf1h[d] = norm[d]   * sum_{s in N(d)} buf0h[s]
// ---------------------------------------------------------------------------
template <int HOP>
__global__ void __launch_bounds__(256) k_hop() {
    int hw   = (blockIdx.x * blockDim.x + threadIdx.x) >> 4;   // node id
    int lane = threadIdx.x & 15;
    if (hw >= N_NODES) return;

    const uint4* in4 = (const uint4*)((HOP == 1) ? g_feath : g_buf0h);

    int beg = g_rowptr[hw];
    int end = g_rowptr[hw + 1];
    float acc[8] = {0.f, 0.f, 0.f, 0.f, 0.f, 0.f, 0.f, 0.f};

#define ACC_U4(u)                                                     \
    do {                                                              \
        __half2* _h = (__half2*)&(u);                                 \
        float2 _f0 = __half22float2(_h[0]);                           \
        float2 _f1 = __half22float2(_h[1]);                           \
        float2 _f2 = __half22float2(_h[2]);                           \
        float2 _f3 = __half22float2(_h[3]);                           \
        acc[0] += _f0.x; acc[1] += _f0.y;                             \
        acc[2] += _f1.x; acc[3] += _f1.y;                             \
        acc[4] += _f2.x; acc[5] += _f2.y;                             \
        acc[6] += _f3.x; acc[7] += _f3.y;                             \
    } while (0)

    int e = beg;
    for (; e + 4 <= end; e += 4) {
        int s0 = __ldg(&g_csr_src[e + 0]), s1 = __ldg(&g_csr_src[e + 1]);
        int s2 = __ldg(&g_csr_src[e + 2]), s3 = __ldg(&g_csr_src[e + 3]);
        uint4 u0 = __ldg(in4 + s0 * 16 + lane);
        uint4 u1 = __ldg(in4 + s1 * 16 + lane);
        uint4 u2 = __ldg(in4 + s2 * 16 + lane);
        uint4 u3 = __ldg(in4 + s3 * 16 + lane);
        ACC_U4(u0);
        ACC_U4(u1);
        ACC_U4(u2);
        ACC_U4(u3);
    }
    for (; e < end; e++) {
        int s = __ldg(&g_csr_src[e]);
        uint4 u = __ldg(in4 + s * 16 + lane);
        ACC_U4(u);
    }
#undef ACC_U4

    float nd = g_norm[hw];
    float scale = (HOP == 1) ? nd * nd : nd;
#pragma unroll
    for (int j = 0; j < 8; j++) acc[j] *= scale;

    __half2 h0 = __floats2half2_rn(acc[0], acc[1]);
    __half2 h1 = __floats2half2_rn(acc[2], acc[3]);
    __half2 h2 = __floats2half2_rn(acc[4], acc[5]);
    __half2 h3 = __floats2half2_rn(acc[6], acc[7]);
    uint4 u;
    u.x = *(unsigned int*)&h0;
    u.y = *(unsigned int*)&h1;
    u.z = *(unsigned int*)&h2;
    u.w = *(unsigned int*)&h3;
    __half* outp = (HOP == 1) ? g_buf0h : g_buf1h;
    ((uint4*)outp)[hw * 16 + lane] = u;
}

// ---------------------------------------------------------------------------
// Tensor-core GEMM: out[n][o] = sum_k A[n][k] * W[o][k] + b[o]
// (R11-proven, ~10us.)
// ---------------------------------------------------------------------------
#define GBM 64
__global__ void __launch_bounds__(256) k_gemm(const float* __restrict__ bias,
                                              float* __restrict__ out) {
    __shared__ float sbias[16][128];

    int t = threadIdx.x;
#pragma unroll
    for (int i = 0; i < 8; i++) {
        int idx = t + i * 256;
        sbias[idx >> 7][idx & 127] = bias[idx & 127];
    }
    __syncthreads();

    int warp = t >> 5;
    int wm = warp >> 1;
    int wn = warp & 1;
    int row0 = blockIdx.x * GBM + wm * 16;
    int col0 = wn * 64;

    wmma::fragment<wmma::accumulator, 16, 16, 16, float> acc[4];
#pragma unroll
    for (int j = 0; j < 4; j++)
        wmma::load_matrix_sync(acc[j], &sbias[0][col0 + j * 16], 128,
                               wmma::mem_row_major);

#pragma unroll
    for (int k0 = 0; k0 < D; k0 += 16) {
        wmma::fragment<wmma::matrix_a, 16, 16, 16, __half, wmma::row_major> a;
        wmma::load_matrix_sync(a, g_buf1h + (size_t)row0 * D + k0, D);
#pragma unroll
        for (int j = 0; j < 4; j++) {
            wmma::fragment<wmma::matrix_b, 16, 16, 16, __half, wmma::col_major> b;
            wmma::load_matrix_sync(b, g_Wh + (size_t)(col0 + j * 16) * D + k0, D);
            wmma::mma_sync(acc[j], a, b, acc[j]);
        }
    }

    if (row0 + 16 <= N_NODES) {
#pragma unroll
        for (int j = 0; j < 4; j++)
            wmma::store_matrix_sync(out + (size_t)row0 * D + col0 + j * 16,
                                    acc[j], D, wmma::mem_row_major);
    }
}

// ---------------------------------------------------------------------------
// kernel_launch
// ---------------------------------------------------------------------------
extern "C" void kernel_launch(void* const* d_in, const int* in_sizes, int n_in,
                              void* d_out, int out_size) {
    const float* feat = (const float*)d_in[0];
    const int*   src  = (const int*)d_in[1];
    const int*   dst  = (const int*)d_in[2];
    const float* W    = (const float*)d_in[3];
    const float* bias = (const float*)d_in[4];
    float*       out  = (float*)d_out;

    const int gEdge = (N_EDGES + 255) / 256;
    const int gFill = (FILL_T + 255) / 256;
    const int gHop  = (N_NODES * 16 + 255) / 256;   // half-warp per node
    const int gGemm = (N_PAD + GBM - 1) / GBM;      // 782

    void* p = nullptr;
    cudaGetSymbolAddress(&p, g_cnt);
    cudaMemsetAsync(p, 0, N_NODES * sizeof(int), 0);

    k_deg_rank<<<gEdge, 256>>>(dst);
    k_scan1   <<<SCAN_NBLK, SCAN_B>>>();
    k_scan2   <<<SCAN_NBLK, SCAN_B>>>(W);        // offsets + norm + W->fp16
    k_fill_cvt<<<gFill, 256>>>(src, dst, feat);  // CSR + feat'*norm fp16 + pad
    k_hop<1>  <<<gHop, 256>>>();                 // g_feath -> g_buf0h
    k_hop<2>  <<<gHop, 256>>>();                 // g_buf0h -> g_buf1h
    k_gemm    <<<gGemm, 256>>>(bias, out);
}